// round 6
// baseline (speedup 1.0000x reference)
#include <cuda_runtime.h>
#include <math.h>
#include <stdint.h>

#define BB 8
#define HH 8
#define PP 4
#define FEAT 64
#define EMB 32
#define HIN 96
#define GH 32
#define TT 101770

#define TPB 256            // 2 threads per t, 128 t per block
#define NT 128             // t's per block
#define AW_STR 100
#define G2_STR 36
#define BUF_FLOATS (NT * AW_STR + NT * G2_STR)   // 17408 floats per head-buffer

// ---------- persistent scratch ----------
__device__ float g_h1    [BB * 128];
__device__ float g_feats [BB * FEAT];
__device__ float g_featsT2[2 * FEAT * 4];   // [half][k][lb]  (lb = b within half)
__device__ float g_embT  [EMB * PP];        // [k][p]
__device__ float g_hmidT [HH * GH * 32];    // [h][j][half][p][lb]
__device__ float g_gate  [HH * BB];         // [h][b]

// ---------- packed f32x2 helpers ----------
__device__ __forceinline__ unsigned long long pk2(float lo, float hi) {
    unsigned long long r;
    asm("mov.b64 %0, {%1, %2};" : "=l"(r) : "f"(lo), "f"(hi));
    return r;
}
__device__ __forceinline__ unsigned long long fma2(unsigned long long a,
                                                   unsigned long long b,
                                                   unsigned long long c) {
    unsigned long long d;
    asm("fma.rn.f32x2 %0, %1, %2, %3;" : "=l"(d) : "l"(a), "l"(b), "l"(c));
    return d;
}
__device__ __forceinline__ void upk2(unsigned long long v, float& lo, float& hi) {
    asm("mov.b64 {%0, %1}, %2;" : "=f"(lo), "=f"(hi) : "l"(v));
}

// ---------- cp.async helpers ----------
__device__ __forceinline__ void cp16(uint32_t dst_smem, const void* src) {
    asm volatile("cp.async.cg.shared.global [%0], [%1], 16;" :: "r"(dst_smem), "l"(src));
}
__device__ __forceinline__ void cp_commit() { asm volatile("cp.async.commit_group;"); }
template<int N>
__device__ __forceinline__ void cp_wait() {
    asm volatile("cp.async.wait_group %0;" :: "n"(N));
}

// ---------- prep 1a: layer 1, one warp per output (128 blocks x 256 thr) ----------
__global__ void __launch_bounds__(256, 1)
prep1a_kernel(const float* __restrict__ x,
              const float* __restrict__ feW1, const float* __restrict__ feb1)
{
    int g = blockIdx.x * 8 + (threadIdx.x >> 5);
    int lane = threadIdx.x & 31;
    int b = g >> 7, j = g & 127;
    const float* xr = x + b * 784;
    const float* wr = feW1 + j * 784;
    float s = 0.f;
    #pragma unroll 4
    for (int i = lane; i < 784; i += 32) s = fmaf(xr[i], wr[i], s);
    #pragma unroll
    for (int o = 16; o; o >>= 1) s += __shfl_down_sync(0xFFFFFFFFu, s, o);
    if (lane == 0) g_h1[b * 128 + j] = fmaxf(s + feb1[j], 0.f);
}

// ---------- prep fuse: layer 2 (redundant per block) + gate + hmid + embT ----------
__global__ void __launch_bounds__(256, 1)
prep_fuse_kernel(const float* __restrict__ feW2, const float* __restrict__ feb2,
                 const float* __restrict__ gateW, const float* __restrict__ gateb,
                 const float* __restrict__ embeds,
                 const float* __restrict__ genW1, const float* __restrict__ genb1)
{
    int h = blockIdx.x;
    int tid = threadIdx.x;
    __shared__ float s_h1[BB * 128];
    __shared__ float s_feats[BB * FEAT];
    __shared__ float s_emb[PP * EMB];

    for (int i = tid; i < BB * 128; i += 256) s_h1[i] = g_h1[i];
    for (int i = tid; i < PP * EMB; i += 256) s_emb[i] = embeds[i];
    __syncthreads();

    // layer 2: 512 outputs, each block computes all (cheap, redundant)
    for (int o = tid; o < BB * FEAT; o += 256) {
        int b = o >> 6, f = o & 63;
        float s = feb2[f];
        const float* hr = s_h1 + b * 128;
        const float* wr = feW2 + f * 128;
        #pragma unroll 8
        for (int j = 0; j < 128; j++) s = fmaf(hr[j], wr[j], s);
        s_feats[b * FEAT + f] = s;
        if (h == 0) {
            g_feats[b * FEAT + f] = s;
            // featsT2[half][k][lb]
            g_featsT2[(b >> 2) * (FEAT * 4) + f * 4 + (b & 3)] = s;
        }
    }
    __syncthreads();

    if (h == 0 && tid < 8) {
        int r = tid;
        float lg[8];
        float mx = -1e30f;
        #pragma unroll
        for (int c = 0; c < 8; c++) {
            float s = gateb[c];
            const float* fr = s_feats + r * FEAT;
            const float* wr = gateW + c * FEAT;
            #pragma unroll 8
            for (int k = 0; k < FEAT; k++) s = fmaf(fr[k], wr[k], s);
            lg[c] = s;
            mx = fmaxf(mx, s);
        }
        float den = 0.f;
        #pragma unroll
        for (int c = 0; c < 8; c++) { lg[c] = __expf(lg[c] - mx); den += lg[c]; }
        float inv = 1.f / den;
        #pragma unroll
        for (int c = 0; c < 8; c++) g_gate[r * 8 + c] = lg[c] * inv;
    }
    if (h == 0) {
        for (int i = tid; i < EMB * PP; i += 256) {
            int k = i >> 2, p = i & 3;
            g_embT[k * 4 + p] = embeds[p * EMB + k];
        }
    }

    // hmid for head h: 1024 outputs -> layout [j][half][p][lb]
    for (int idx = tid; idx < GH * 32; idx += 256) {
        int j = idx >> 5;
        int pb = idx & 31;
        int p = pb >> 3, b = pb & 7;
        const float* w = genW1 + (size_t)(h * GH + j) * HIN;
        float s = genb1[h * GH + j];
        const float* fr = s_feats + b * FEAT;
        #pragma unroll 8
        for (int i = 0; i < FEAT; i++) s = fmaf(fr[i], w[i], s);
        const float* er = s_emb + p * EMB;
        #pragma unroll 8
        for (int i = 0; i < EMB; i++) s = fmaf(er[i], w[FEAT + i], s);
        g_hmidT[(h * GH + j) * 32 + (b >> 2) * 16 + p * 4 + (b & 3)] = fmaxf(s, 0.f);
    }
}

// ---------- main kernel: cp.async double-buffered, 2 threads per t ----------
__global__ void __launch_bounds__(TPB)
main_kernel(const float* __restrict__ genW2, const float* __restrict__ genb2,
            const float* __restrict__ attW,  const float* __restrict__ attb,
            float* __restrict__ out)
{
    extern __shared__ float sm[];
    float* sh_buf    = sm;                           // 2 * BUF_FLOATS
    float* sh_hmidT  = sm + 2 * BUF_FLOATS;          // 8192
    float* sh_featsT = sh_hmidT + HH * GH * 32;      // 512
    float* sh_embT   = sh_featsT + 2 * FEAT * 4;     // 128
    float* sh_gate   = sh_embT + EMB * PP;           // 64

    int tid = threadIdx.x;
    int tl  = tid >> 1;          // local t index 0..127
    int half = tid & 1;          // b-half: b in [half*4, half*4+4)
    int t_base = blockIdx.x * NT;
    int t = t_base + tl;
    int tc = (t < TT) ? t : (TT - 1);

    uint32_t smem_u32 = (uint32_t)__cvta_generic_to_shared(sm);

    auto issue_head = [&](int h, int buf) {
        uint32_t base = smem_u32 + (uint32_t)buf * (BUF_FLOATS * 4);
        const float* src = attW + (size_t)h * TT * HIN;
        #pragma unroll
        for (int i = 0; i < 12; i++) {
            int v = tid + i * TPB;              // [0, 3072)
            int row = v / 24, c4 = v % 24;
            int tr = t_base + row; if (tr >= TT) tr = TT - 1;
            cp16(base + (uint32_t)(row * AW_STR + c4 * 4) * 4,
                 src + (size_t)tr * HIN + c4 * 4);
        }
        uint32_t base2 = base + (uint32_t)(NT * AW_STR) * 4;
        const float* src2 = genW2 + (size_t)h * TT * GH;
        #pragma unroll
        for (int i = 0; i < 4; i++) {
            int v = tid + i * TPB;              // [0, 1024)
            int row = v >> 3, c4 = v & 7;
            int tr = t_base + row; if (tr >= TT) tr = TT - 1;
            cp16(base2 + (uint32_t)(row * G2_STR + c4 * 4) * 4,
                 src2 + (size_t)tr * GH + c4 * 4);
        }
    };

    issue_head(0, 0);
    cp_commit();

    // per-t biases for all heads (front-batched LDGs; pairwise dup -> L1 hit)
    float abv[8], b2vv[8];
    #pragma unroll
    for (int h = 0; h < HH; h++) {
        abv[h]  = __ldg(attb  + (size_t)h * TT + tc);
        b2vv[h] = __ldg(genb2 + (size_t)h * TT + tc);
    }

    for (int i = tid; i < HH * GH * 32; i += TPB) sh_hmidT[i] = g_hmidT[i];
    for (int i = tid; i < 2 * FEAT * 4; i += TPB) sh_featsT[i] = g_featsT2[i];
    if (tid < EMB * PP) sh_embT[tid] = g_embT[tid];
    if (tid < HH * BB)  sh_gate[tid] = g_gate[tid];

    float acc[16];
    #pragma unroll
    for (int i = 0; i < 16; i++) acc[i] = 0.f;

    const float* ftq = sh_featsT + half * (FEAT * 4);

    for (int h = 0; h < HH; h++) {
        if (h < HH - 1) {
            issue_head(h + 1, (h + 1) & 1);
            cp_commit();
            cp_wait<1>();
        } else {
            cp_wait<0>();
        }
        __syncthreads();

        const float* mybuf = sh_buf + (h & 1) * BUF_FLOATS;
        const float* myw = mybuf + tl * AW_STR;
        const float* myg = mybuf + NT * AW_STR + tl * G2_STR;

        unsigned long long A2[4], E2[4], W2r[8];
        #pragma unroll
        for (int d = 0; d < 4; d++) { A2[d] = 0ull; E2[d] = 0ull; }
        #pragma unroll
        for (int q = 0; q < 8; q++) W2r[q] = 0ull;

        // ---- A: partial dots feats[b].attW[0:64] for this thread's 4 b ----
        #pragma unroll
        for (int k0 = 0; k0 < 64; k0 += 4) {
            float4 w4 = *reinterpret_cast<const float4*>(myw + k0);
            float wv[4] = {w4.x, w4.y, w4.z, w4.w};
            int sel = (k0 >> 2) & 1;           // split chains for ILP-4
            #pragma unroll
            for (int kk = 0; kk < 4; kk++) {
                unsigned long long wp = pk2(wv[kk], wv[kk]);
                const unsigned long long* f2 =
                    reinterpret_cast<const unsigned long long*>(ftq + (k0 + kk) * 4);
                A2[sel * 2 + 0] = fma2(f2[0], wp, A2[sel * 2 + 0]);
                A2[sel * 2 + 1] = fma2(f2[1], wp, A2[sel * 2 + 1]);
            }
        }
        // ---- E: embeds[p].attW[64:96] for all 4 p ----
        #pragma unroll
        for (int k0 = 0; k0 < 32; k0 += 4) {
            float4 w4 = *reinterpret_cast<const float4*>(myw + 64 + k0);
            float wv[4] = {w4.x, w4.y, w4.z, w4.w};
            int sel = (k0 >> 2) & 1;
            #pragma unroll
            for (int kk = 0; kk < 4; kk++) {
                unsigned long long wp = pk2(wv[kk], wv[kk]);
                const unsigned long long* e2 =
                    reinterpret_cast<const unsigned long long*>(sh_embT + (k0 + kk) * 4);
                E2[sel * 2 + 0] = fma2(e2[0], wp, E2[sel * 2 + 0]);
                E2[sel * 2 + 1] = fma2(e2[1], wp, E2[sel * 2 + 1]);
            }
        }
        // ---- W: hmid[h,pb,:].genW2[h,t,:] for this thread's 16 pb ----
        #pragma unroll
        for (int j0 = 0; j0 < 32; j0 += 4) {
            float4 g4 = *reinterpret_cast<const float4*>(myg + j0);
            float gv[4] = {g4.x, g4.y, g4.z, g4.w};
            #pragma unroll
            for (int jj = 0; jj < 4; jj++) {
                unsigned long long gp = pk2(gv[jj], gv[jj]);
                const unsigned long long* m2 =
                    reinterpret_cast<const unsigned long long*>(
                        sh_hmidT + (h * GH + j0 + jj) * 32 + half * 16);
                #pragma unroll
                for (int q = 0; q < 8; q++) W2r[q] = fma2(m2[q], gp, W2r[q]);
            }
        }

        // ---- epilogue ----
        float ab  = abv[h];
        float b2v = b2vv[h];
        float A[4], E[4];
        {
            float a0, a1, b0, b1;
            upk2(A2[0], a0, a1); upk2(A2[2], b0, b1); A[0] = a0 + b0; A[1] = a1 + b1;
            upk2(A2[1], a0, a1); upk2(A2[3], b0, b1); A[2] = a0 + b0; A[3] = a1 + b1;
            upk2(E2[0], a0, a1); upk2(E2[2], b0, b1); E[0] = a0 + b0; E[1] = a1 + b1;
            upk2(E2[1], a0, a1); upk2(E2[3], b0, b1); E[2] = a0 + b0; E[3] = a1 + b1;
        }
        const float* gr = sh_gate + h * BB + half * 4;
        #pragma unroll
        for (int q = 0; q < 8; q++) {
            float w0, w1;
            upk2(W2r[q], w0, w1);
            int p  = q >> 1;
            int lb0 = (q & 1) * 2;
            float z0 = A[lb0]     + E[p] + ab;
            float z1 = A[lb0 + 1] + E[p] + ab;
            float i0 = __fdividef(1.f, 1.f + __expf(-z0));
            float i1 = __fdividef(1.f, 1.f + __expf(-z1));
            acc[p * 4 + lb0]     = fmaf((w0 + b2v) * i0, gr[lb0],     acc[p * 4 + lb0]);
            acc[p * 4 + lb0 + 1] = fmaf((w1 + b2v) * i1, gr[lb0 + 1], acc[p * 4 + lb0 + 1]);
        }

        __syncthreads();
    }

    if (t < TT) {
        #pragma unroll
        for (int p = 0; p < PP; p++) {
            #pragma unroll
            for (int lb = 0; lb < 4; lb++) {
                int b = half * 4 + lb;
                out[(size_t)b * (PP * TT) + (size_t)p * TT + t] = acc[p * 4 + lb];
            }
        }
    }
}

extern "C" void kernel_launch(void* const* d_in, const int* in_sizes, int n_in,
                              void* d_out, int out_size)
{
    const float* x     = (const float*)d_in[0];
    const float* feW1  = (const float*)d_in[1];
    const float* feb1  = (const float*)d_in[2];
    const float* feW2  = (const float*)d_in[3];
    const float* feb2  = (const float*)d_in[4];
    const float* emb   = (const float*)d_in[5];
    const float* genW1 = (const float*)d_in[6];
    const float* genb1 = (const float*)d_in[7];
    const float* genW2 = (const float*)d_in[8];
    const float* genb2 = (const float*)d_in[9];
    const float* attW  = (const float*)d_in[10];
    const float* attb  = (const float*)d_in[11];
    const float* gateW = (const float*)d_in[12];
    const float* gateb = (const float*)d_in[13];
    float* out = (float*)d_out;

    prep1a_kernel<<<128, 256>>>(x, feW1, feb1);
    prep_fuse_kernel<<<8, 256>>>(feW2, feb2, gateW, gateb, emb, genW1, genb1);

    const int SMEM = (2 * BUF_FLOATS + HH * GH * 32 + 2 * FEAT * 4 + EMB * PP + HH * BB) * 4;
    cudaFuncSetAttribute(main_kernel, cudaFuncAttributeMaxDynamicSharedMemorySize, SMEM);
    int grid = (TT + NT - 1) / NT;
    main_kernel<<<grid, TPB, SMEM>>>(genW2, genb2, attW, attb, out);
}

// round 8
// speedup vs baseline: 1.2346x; 1.2346x over previous
#include <cuda_runtime.h>
#include <math.h>
#include <stdint.h>

#define BB 8
#define HH 8
#define PP 4
#define FEAT 64
#define EMB 32
#define HIN 96
#define GH 32
#define TT 101770

#define TPB 128
#define NT 128
#define AW_STR 100                      // padded stride for staged att_W rows
#define AWBUF (NT * AW_STR)             // 12800 floats per attW buffer
#define HMBUF (GH * 32)                 // 1024 floats per hmid slice

// ---------- persistent scratch ----------
__device__ float g_h1    [BB * 128];
__device__ float g_feats [BB * FEAT];
__device__ float g_featsT[FEAT * BB];   // [k][b]
__device__ float g_embT  [EMB * PP];    // [k][p]
__device__ float g_hmidT [HH * GH * 32];// [h][j][pb]
__device__ float g_gate  [HH * BB];     // [h][b]

// ---------- packed f32x2 helpers ----------
__device__ __forceinline__ unsigned long long pk2(float lo, float hi) {
    unsigned long long r;
    asm("mov.b64 %0, {%1, %2};" : "=l"(r) : "f"(lo), "f"(hi));
    return r;
}
__device__ __forceinline__ unsigned long long fma2(unsigned long long a,
                                                   unsigned long long b,
                                                   unsigned long long c) {
    unsigned long long d;
    asm("fma.rn.f32x2 %0, %1, %2, %3;" : "=l"(d) : "l"(a), "l"(b), "l"(c));
    return d;
}
__device__ __forceinline__ void upk2(unsigned long long v, float& lo, float& hi) {
    asm("mov.b64 {%0, %1}, %2;" : "=f"(lo), "=f"(hi) : "l"(v));
}

// ---------- cp.async helpers ----------
__device__ __forceinline__ void cp16(uint32_t dst_smem, const void* src) {
    asm volatile("cp.async.cg.shared.global [%0], [%1], 16;" :: "r"(dst_smem), "l"(src));
}
__device__ __forceinline__ void cp_commit() { asm volatile("cp.async.commit_group;"); }
template<int N>
__device__ __forceinline__ void cp_wait() {
    asm volatile("cp.async.wait_group %0;" :: "n"(N));
}

// ---------- prep 1a: layer 1, one warp per output (128 blocks x 256 thr) ----------
__global__ void __launch_bounds__(256, 1)
prep1a_kernel(const float* __restrict__ x,
              const float* __restrict__ feW1, const float* __restrict__ feb1)
{
    int g = blockIdx.x * 8 + (threadIdx.x >> 5);
    int lane = threadIdx.x & 31;
    int b = g >> 7, j = g & 127;
    const float* xr = x + b * 784;
    const float* wr = feW1 + j * 784;
    float s = 0.f;
    #pragma unroll 4
    for (int i = lane; i < 784; i += 32) s = fmaf(xr[i], wr[i], s);
    #pragma unroll
    for (int o = 16; o; o >>= 1) s += __shfl_down_sync(0xFFFFFFFFu, s, o);
    if (lane == 0) g_h1[b * 128 + j] = fmaxf(s + feb1[j], 0.f);
}

// ---------- prep fuse: layer 2 (redundant per block) + gate + hmid + embT ----------
__global__ void __launch_bounds__(256, 1)
prep_fuse_kernel(const float* __restrict__ feW2, const float* __restrict__ feb2,
                 const float* __restrict__ gateW, const float* __restrict__ gateb,
                 const float* __restrict__ embeds,
                 const float* __restrict__ genW1, const float* __restrict__ genb1)
{
    int h = blockIdx.x;
    int tid = threadIdx.x;
    __shared__ float s_h1[BB * 128];
    __shared__ float s_feats[BB * FEAT];
    __shared__ float s_emb[PP * EMB];

    for (int i = tid; i < BB * 128; i += 256) s_h1[i] = g_h1[i];
    for (int i = tid; i < PP * EMB; i += 256) s_emb[i] = embeds[i];
    __syncthreads();

    for (int o = tid; o < BB * FEAT; o += 256) {
        int b = o >> 6, f = o & 63;
        float s = feb2[f];
        const float* hr = s_h1 + b * 128;
        const float* wr = feW2 + f * 128;
        #pragma unroll 8
        for (int j = 0; j < 128; j++) s = fmaf(hr[j], wr[j], s);
        s_feats[b * FEAT + f] = s;
        if (h == 0) {
            g_feats[b * FEAT + f] = s;
            g_featsT[f * BB + b] = s;
        }
    }
    __syncthreads();

    if (h == 0 && tid < 8) {
        int r = tid;
        float lg[8];
        float mx = -1e30f;
        #pragma unroll
        for (int c = 0; c < 8; c++) {
            float s = gateb[c];
            const float* fr = s_feats + r * FEAT;
            const float* wr = gateW + c * FEAT;
            #pragma unroll 8
            for (int k = 0; k < FEAT; k++) s = fmaf(fr[k], wr[k], s);
            lg[c] = s;
            mx = fmaxf(mx, s);
        }
        float den = 0.f;
        #pragma unroll
        for (int c = 0; c < 8; c++) { lg[c] = __expf(lg[c] - mx); den += lg[c]; }
        float inv = 1.f / den;
        #pragma unroll
        for (int c = 0; c < 8; c++) g_gate[r * 8 + c] = lg[c] * inv;
    }
    if (h == 0) {
        for (int i = tid; i < EMB * PP; i += 256) {
            int k = i >> 2, p = i & 3;
            g_embT[k * 4 + p] = embeds[p * EMB + k];
        }
    }

    // hmid for head h: layout [j][pb]
    for (int idx = tid; idx < GH * 32; idx += 256) {
        int j = idx >> 5;
        int pb = idx & 31;
        int p = pb >> 3, b = pb & 7;
        const float* w = genW1 + (size_t)(h * GH + j) * HIN;
        float s = genb1[h * GH + j];
        const float* fr = s_feats + b * FEAT;
        #pragma unroll 8
        for (int i = 0; i < FEAT; i++) s = fmaf(fr[i], w[i], s);
        const float* er = s_emb + p * EMB;
        #pragma unroll 8
        for (int i = 0; i < EMB; i++) s = fmaf(er[i], w[FEAT + i], s);
        g_hmidT[(h * GH + j) * 32 + pb] = fmaxf(s, 0.f);
    }
}

// ---------- main kernel: 2 blocks/SM, cp.async double-buffered attW+hmid,
//            genW2 register-prefetched one head ahead ----------
__global__ void __launch_bounds__(TPB, 2)
main_kernel(const float* __restrict__ genW2, const float* __restrict__ genb2,
            const float* __restrict__ attW,  const float* __restrict__ attb,
            float* __restrict__ out)
{
    extern __shared__ float sm[];
    float* sh_attw   = sm;                          // 2 * 12800
    float* sh_hmid   = sm + 2 * AWBUF;              // 2 * 1024
    float* sh_featsT = sh_hmid + 2 * HMBUF;         // 512
    float* sh_embT   = sh_featsT + FEAT * BB;       // 128
    float* sh_gate   = sh_embT + EMB * PP;          // 64

    int tid = threadIdx.x;
    int t_base = blockIdx.x * NT;
    int t = t_base + tid;
    int tc = (t < TT) ? t : (TT - 1);

    uint32_t smem_u32 = (uint32_t)__cvta_generic_to_shared(sm);

    // stage attW tile + hmid slice for head h into buffer `buf`
    auto issue_head = [&](int h, int buf) {
        uint32_t base = smem_u32 + (uint32_t)buf * (AWBUF * 4);
        const float* src = attW + (size_t)h * TT * HIN;
        #pragma unroll
        for (int i = 0; i < 24; i++) {
            int v = tid + i * TPB;              // [0, 3072)
            int row = v / 24, c4 = v % 24;
            int tr = t_base + row; if (tr >= TT) tr = TT - 1;
            cp16(base + (uint32_t)(row * AW_STR + c4 * 4) * 4,
                 src + (size_t)tr * HIN + c4 * 4);
        }
        uint32_t hb = smem_u32 + (uint32_t)(2 * AWBUF + buf * HMBUF) * 4;
        const float* hsrc = g_hmidT + (size_t)h * HMBUF;
        #pragma unroll
        for (int i = 0; i < 2; i++) {
            int v = tid + i * TPB;              // [0, 256) float4s
            cp16(hb + (uint32_t)v * 16, hsrc + v * 4);
        }
    };

    issue_head(0, 0);
    cp_commit();

    // per-t biases for all heads
    float abv[8], b2vv[8];
    #pragma unroll
    for (int h = 0; h < HH; h++) {
        abv[h]  = __ldg(attb  + (size_t)h * TT + tc);
        b2vv[h] = __ldg(genb2 + (size_t)h * TT + tc);
    }

    // genW2 row prefetch for head 0
    float4 gw[8];
    {
        const float4* gsrc = reinterpret_cast<const float4*>(genW2 + (size_t)tc * GH);
        #pragma unroll
        for (int i = 0; i < 8; i++) gw[i] = __ldg(gsrc + i);
    }

    // small persistent tables
    for (int i = tid; i < FEAT * BB; i += TPB) sh_featsT[i] = g_featsT[i];
    if (tid < EMB * PP) sh_embT[tid] = g_embT[tid];
    if (tid < HH * BB)  sh_gate[tid] = g_gate[tid];

    float acc[32];
    #pragma unroll
    for (int i = 0; i < 32; i++) acc[i] = 0.f;

    for (int h = 0; h < HH; h++) {
        if (h < HH - 1) {
            issue_head(h + 1, (h + 1) & 1);
            cp_commit();
            cp_wait<1>();
        } else {
            cp_wait<0>();
        }
        __syncthreads();

        const float* myw   = sh_attw + (h & 1) * AWBUF + tid * AW_STR;
        const float* hmidb = sh_hmid + (h & 1) * HMBUF;

        // ---- W part first: consumes prefetched gw registers ----
        unsigned long long W2r[16];
        #pragma unroll
        for (int q = 0; q < 16; q++) W2r[q] = 0ull;
        #pragma unroll
        for (int j0 = 0; j0 < 8; j0++) {
            float gv[4] = {gw[j0].x, gw[j0].y, gw[j0].z, gw[j0].w};
            #pragma unroll
            for (int jj = 0; jj < 4; jj++) {
                unsigned long long gp = pk2(gv[jj], gv[jj]);
                const unsigned long long* m2 =
                    reinterpret_cast<const unsigned long long*>(hmidb + (j0 * 4 + jj) * 32);
                #pragma unroll
                for (int q = 0; q < 16; q++) W2r[q] = fma2(m2[q], gp, W2r[q]);
            }
        }

        // ---- prefetch genW2 row for next head (latency hidden by A/E) ----
        if (h < HH - 1) {
            const float4* gsrc =
                reinterpret_cast<const float4*>(genW2 + (size_t)(h + 1) * TT * GH + (size_t)tc * GH);
            #pragma unroll
            for (int i = 0; i < 8; i++) gw[i] = __ldg(gsrc + i);
        }

        // ---- A part: A[b] = feats[b] . attW[h,t,0:64] ----
        unsigned long long A2[4], E2[2];
        #pragma unroll
        for (int d = 0; d < 4; d++) A2[d] = 0ull;
        E2[0] = 0ull; E2[1] = 0ull;
        #pragma unroll
        for (int k0 = 0; k0 < 64; k0 += 4) {
            float4 w4 = *reinterpret_cast<const float4*>(myw + k0);
            float wv[4] = {w4.x, w4.y, w4.z, w4.w};
            #pragma unroll
            for (int kk = 0; kk < 4; kk++) {
                unsigned long long wp = pk2(wv[kk], wv[kk]);
                const unsigned long long* f2 =
                    reinterpret_cast<const unsigned long long*>(sh_featsT + (k0 + kk) * BB);
                #pragma unroll
                for (int d = 0; d < 4; d++) A2[d] = fma2(f2[d], wp, A2[d]);
            }
        }
        // ---- E part: E[p] = embeds[p] . attW[h,t,64:96] ----
        #pragma unroll
        for (int k0 = 0; k0 < 32; k0 += 4) {
            float4 w4 = *reinterpret_cast<const float4*>(myw + 64 + k0);
            float wv[4] = {w4.x, w4.y, w4.z, w4.w};
            #pragma unroll
            for (int kk = 0; kk < 4; kk++) {
                unsigned long long wp = pk2(wv[kk], wv[kk]);
                const unsigned long long* e2 =
                    reinterpret_cast<const unsigned long long*>(sh_embT + (k0 + kk) * PP);
                E2[0] = fma2(e2[0], wp, E2[0]);
                E2[1] = fma2(e2[1], wp, E2[1]);
            }
        }

        // ---- epilogue ----
        float ab  = abv[h];
        float b2v = b2vv[h];
        float A[8], E[4];
        #pragma unroll
        for (int d = 0; d < 4; d++) upk2(A2[d], A[2 * d], A[2 * d + 1]);
        upk2(E2[0], E[0], E[1]);
        upk2(E2[1], E[2], E[3]);
        const float* gr = sh_gate + h * BB;
        #pragma unroll
        for (int q = 0; q < 16; q++) {
            float w0, w1;
            upk2(W2r[q], w0, w1);
            int pb0 = 2 * q;
            int b0 = pb0 & 7;
            int p  = pb0 >> 3;
            float z0 = A[b0]     + E[p] + ab;
            float z1 = A[b0 + 1] + E[p] + ab;
            float i0 = __fdividef(1.f, 1.f + __expf(-z0));
            float i1 = __fdividef(1.f, 1.f + __expf(-z1));
            acc[pb0]     = fmaf((w0 + b2v) * i0, gr[b0],     acc[pb0]);
            acc[pb0 + 1] = fmaf((w1 + b2v) * i1, gr[b0 + 1], acc[pb0 + 1]);
        }

        __syncthreads();   // readers done before next issue overwrites buffer
    }

    if (t < TT) {
        #pragma unroll
        for (int pb = 0; pb < 32; pb++) {
            int p = pb >> 3, b = pb & 7;
            out[(size_t)b * (PP * TT) + (size_t)p * TT + t] = acc[pb];
        }
    }
}

extern "C" void kernel_launch(void* const* d_in, const int* in_sizes, int n_in,
                              void* d_out, int out_size)
{
    const float* x     = (const float*)d_in[0];
    const float* feW1  = (const float*)d_in[1];
    const float* feb1  = (const float*)d_in[2];
    const float* feW2  = (const float*)d_in[3];
    const float* feb2  = (const float*)d_in[4];
    const float* emb   = (const float*)d_in[5];
    const float* genW1 = (const float*)d_in[6];
    const float* genb1 = (const float*)d_in[7];
    const float* genW2 = (const float*)d_in[8];
    const float* genb2 = (const float*)d_in[9];
    const float* attW  = (const float*)d_in[10];
    const float* attb  = (const float*)d_in[11];
    const float* gateW = (const float*)d_in[12];
    const float* gateb = (const float*)d_in[13];
    float* out = (float*)d_out;

    prep1a_kernel<<<128, 256>>>(x, feW1, feb1);
    prep_fuse_kernel<<<8, 256>>>(feW2, feb2, gateW, gateb, emb, genW1, genb1);

    const int SMEM = (2 * AWBUF + 2 * HMBUF + FEAT * BB + EMB * PP + HH * BB) * 4;
    cudaFuncSetAttribute(main_kernel, cudaFuncAttributeMaxDynamicSharedMemorySize, SMEM);
    int grid = (TT + NT - 1) / NT;
    main_kernel<<<grid, TPB, SMEM>>>(genW2, genb2, attW, attb, out);
}